// round 1
// baseline (speedup 1.0000x reference)
#include <cuda_runtime.h>

// Problem constants
constexpr int B_  = 4;
constexpr int N_  = 2048;
constexpr int M_  = 2048;
constexpr int DM_ = 512;
constexpr int H_  = 8;
constexpr int DH_ = 64;
constexpr int HD_ = 512;   // H*DH == DO

// Scratch (static device globals: allowed; no runtime allocation)
__device__ float g_q[B_ * H_ * N_ * DH_];     // [B,H,N,DH], pre-scaled by 1/8
__device__ float g_k[B_ * H_ * M_ * DH_];     // [B,H,M,DH]
__device__ float g_v[B_ * H_ * M_ * DH_];     // [B,H,M,DH]
__device__ float g_mh[B_ * N_ * HD_];         // [B,N,H*DH]
__device__ float g_wp[3 * DM_ * HD_];         // repacked QKV weights, [sel][i][h*64+d]
__device__ float g_bp[3 * HD_];               // repacked QKV biases

// ---------------------------------------------------------------------------
// Repack [H, DM, DH] weights -> [DM, H*DH] row-major; biases [H,DH] -> [H*DH]
// ---------------------------------------------------------------------------
__global__ void repack_kernel(const float* __restrict__ wq, const float* __restrict__ wk,
                              const float* __restrict__ wv, const float* __restrict__ bq,
                              const float* __restrict__ bk, const float* __restrict__ bv)
{
    int idx = blockIdx.x * 256 + threadIdx.x;
    if (idx < 3 * DM_ * HD_) {
        int sel = idx / (DM_ * HD_);
        int rem = idx - sel * (DM_ * HD_);
        int i = rem / HD_;
        int j = rem - i * HD_;
        const float* w = (sel == 0) ? wq : (sel == 1 ? wk : wv);
        g_wp[idx] = w[(j >> 6) * (DM_ * DH_) + i * DH_ + (j & 63)];
    }
    if (idx < 3 * HD_) {
        int sel = idx / HD_;
        int j = idx - sel * HD_;
        const float* bb = (sel == 0) ? bq : (sel == 1 ? bk : bv);
        g_bp[idx] = bb[j];
    }
}

// ---------------------------------------------------------------------------
// Shared GEMM mainloop: C[128x128] += A[rows,512] * W[512,512] tile product.
// 256 threads, 8x8 micro-tile per thread, BK=16.
// ---------------------------------------------------------------------------
__device__ __forceinline__ void gemm_mainloop(const float* __restrict__ A,
                                              const float* __restrict__ W,
                                              float (*As)[132], float (*Bs)[128],
                                              float acc[8][8], int row0, int col0,
                                              int tx, int ty)
{
    int tid = threadIdx.x;
    for (int k0 = 0; k0 < DM_; k0 += 16) {
        #pragma unroll
        for (int t = 0; t < 2; t++) {
            int idx = tid + t * 256;          // 0..511 over 512 float4s (128x16)
            int ar = idx >> 2;                // 0..127
            int ac = (idx & 3) * 4;           // 0..12
            float4 v = *(const float4*)&A[(row0 + ar) * DM_ + k0 + ac];
            As[ac + 0][ar] = v.x;
            As[ac + 1][ar] = v.y;
            As[ac + 2][ar] = v.z;
            As[ac + 3][ar] = v.w;
        }
        #pragma unroll
        for (int t = 0; t < 2; t++) {
            int idx = tid + t * 256;          // 0..511 over 512 float4s (16x128)
            int br = idx >> 5;                // 0..15
            int bc = (idx & 31) * 4;          // 0..124
            *(float4*)&Bs[br][bc] = *(const float4*)&W[(k0 + br) * HD_ + col0 + bc];
        }
        __syncthreads();
        #pragma unroll
        for (int kk = 0; kk < 16; kk++) {
            float a[8], b[8];
            *(float4*)&a[0] = *(const float4*)&As[kk][ty * 8];
            *(float4*)&a[4] = *(const float4*)&As[kk][ty * 8 + 4];
            *(float4*)&b[0] = *(const float4*)&Bs[kk][tx * 8];
            *(float4*)&b[4] = *(const float4*)&Bs[kk][tx * 8 + 4];
            #pragma unroll
            for (int i = 0; i < 8; i++)
                #pragma unroll
                for (int j = 0; j < 8; j++)
                    acc[i][j] = fmaf(a[i], b[j], acc[i][j]);
        }
        __syncthreads();
    }
}

// ---------------------------------------------------------------------------
// QKV projection: one launch, blockIdx.z selects q/k/v.
// Output layout [B,H,seq,DH]; q gets bias then *0.125 (= 1/sqrt(DH)).
// ---------------------------------------------------------------------------
__global__ __launch_bounds__(256) void gemm_qkv_kernel(const float* __restrict__ Aq,
                                                       const float* __restrict__ Ak,
                                                       const float* __restrict__ Av)
{
    __shared__ float As[16][132];
    __shared__ float Bs[16][128];

    int sel = blockIdx.z;
    const float* A = (sel == 0) ? Aq : (sel == 1 ? Ak : Av);
    const float* W = g_wp + sel * (DM_ * HD_);
    const float* bias = g_bp + sel * HD_;
    float* out = (sel == 0) ? g_q : (sel == 1 ? g_k : g_v);
    float scale = (sel == 0) ? 0.125f : 1.0f;

    int tid = threadIdx.x;
    int tx = tid & 15, ty = tid >> 4;
    int row0 = blockIdx.y * 128;
    int col0 = blockIdx.x * 128;

    float acc[8][8] = {};
    gemm_mainloop(A, W, As, Bs, acc, row0, col0, tx, ty);

    int gc = col0 + tx * 8;
    int h = gc >> 6;
    int d = gc & 63;                 // 8 consecutive d's within one head (8-aligned)
    float bj[8];
    #pragma unroll
    for (int j = 0; j < 8; j++) bj[j] = bias[gc + j];

    #pragma unroll
    for (int i = 0; i < 8; i++) {
        int gr = row0 + ty * 8 + i;
        int b = gr >> 11;
        int n = gr & 2047;
        float v[8];
        #pragma unroll
        for (int j = 0; j < 8; j++) v[j] = (acc[i][j] + bj[j]) * scale;
        float* op = &out[(((b * H_ + h) * N_ + n) * DH_) + d];
        *(float4*)&op[0] = *(float4*)&v[0];
        *(float4*)&op[4] = *(float4*)&v[4];
    }
}

// ---------------------------------------------------------------------------
// Output projection: g_mh[8192,512] x projection_kernel[512,512] + bias -> out
// (projection_kernel [H,DH,DO] flattens to row-major [H*DH, DO] directly)
// ---------------------------------------------------------------------------
__global__ __launch_bounds__(256) void gemm_proj_kernel(const float* __restrict__ W,
                                                        const float* __restrict__ bias,
                                                        float* __restrict__ out)
{
    __shared__ float As[16][132];
    __shared__ float Bs[16][128];

    int tid = threadIdx.x;
    int tx = tid & 15, ty = tid >> 4;
    int row0 = blockIdx.y * 128;
    int col0 = blockIdx.x * 128;

    float acc[8][8] = {};
    gemm_mainloop(g_mh, W, As, Bs, acc, row0, col0, tx, ty);

    int gc = col0 + tx * 8;
    float bj[8];
    #pragma unroll
    for (int j = 0; j < 8; j++) bj[j] = bias[gc + j];

    #pragma unroll
    for (int i = 0; i < 8; i++) {
        int gr = row0 + ty * 8 + i;
        float v[8];
        #pragma unroll
        for (int j = 0; j < 8; j++) v[j] = acc[i][j] + bj[j];
        float* op = &out[gr * HD_ + gc];
        *(float4*)&op[0] = *(float4*)&v[0];
        *(float4*)&op[4] = *(float4*)&v[4];
    }
}

// ---------------------------------------------------------------------------
// Flash attention: per (b, h, 64-query tile). 256 threads, 4x4 micro-tiles.
// Q and K are stored k-major in smem; K/P share a buffer with an XOR swizzle
// (group g at row kk lives at g^(kk&15)) so all fragment reads are
// conflict-free float4s and total static smem is exactly 48 KB.
// ---------------------------------------------------------------------------
__global__ __launch_bounds__(256) void flash_kernel()
{
    __shared__ float Qts[64][64];   // [d][qrow]
    __shared__ float KP[64][64];    // [d][key] (swizzled) then [key][qrow] (swizzled)
    __shared__ float Vs[64][64];    // [key][d]

    int tid = threadIdx.x;
    int tx = tid & 15, ty = tid >> 4;
    int nt = blockIdx.x, h = blockIdx.y, b = blockIdx.z;

    const float* qg = g_q + ((b * H_ + h) * N_ + nt * 64) * DH_;
    const float* kg = g_k + (b * H_ + h) * (M_ * DH_);
    const float* vg = g_v + (b * H_ + h) * (M_ * DH_);

    // Load Q tile transposed (once per block; store conflicts negligible)
    #pragma unroll
    for (int t = 0; t < 4; t++) {
        int idx = tid + t * 256;      // 0..1023 over 64x16 float4s
        int r = idx >> 4;             // query row 0..63
        int c = (idx & 15) * 4;       // d base
        float4 v = *(const float4*)&qg[r * 64 + c];
        Qts[c + 0][r] = v.x;
        Qts[c + 1][r] = v.y;
        Qts[c + 2][r] = v.z;
        Qts[c + 3][r] = v.w;
    }

    float o[4][4] = {};
    float m_prev[4], l[4];
    #pragma unroll
    for (int i = 0; i < 4; i++) { m_prev[i] = -1e30f; l[i] = 0.0f; }

    __syncthreads();

    for (int mt = 0; mt < M_; mt += 64) {
        // Load K (transposed + swizzled) and V (natural)
        #pragma unroll
        for (int t = 0; t < 4; t++) {
            int idx = tid + t * 256;
            int r = idx >> 4;          // key row 0..63
            int c = (idx & 15) * 4;    // d base
            float4 kv = *(const float4*)&kg[(mt + r) * 64 + c];
            float* kvp = (float*)&kv;
            #pragma unroll
            for (int u = 0; u < 4; u++) {
                int kr = c + u;
                KP[kr][4 * ((r >> 2) ^ (kr & 15)) + (r & 3)] = kvp[u];
            }
            *(float4*)&Vs[r][c] = *(const float4*)&vg[(mt + r) * 64 + c];
        }
        __syncthreads();

        // S = Q * K^T  (rows ty*4+i, cols tx*4+j)
        float s[4][4] = {};
        #pragma unroll 16
        for (int kk = 0; kk < 64; kk++) {
            float4 af = *(const float4*)&Qts[kk][ty * 4];
            float4 bf = *(const float4*)&KP[kk][4 * (tx ^ (kk & 15))];
            float* ap = (float*)&af;
            float* bp = (float*)&bf;
            #pragma unroll
            for (int i = 0; i < 4; i++)
                #pragma unroll
                for (int j = 0; j < 4; j++)
                    s[i][j] = fmaf(ap[i], bp[j], s[i][j]);
        }

        // Online softmax (row r = ty*4+i is spread across the 16 tx lanes,
        // which share a warp half: shuffles with off<16 stay in-row)
        #pragma unroll
        for (int i = 0; i < 4; i++) {
            float mx = fmaxf(fmaxf(s[i][0], s[i][1]), fmaxf(s[i][2], s[i][3]));
            #pragma unroll
            for (int off = 1; off < 16; off <<= 1)
                mx = fmaxf(mx, __shfl_xor_sync(0xffffffffu, mx, off));
            float mn = fmaxf(m_prev[i], mx);
            float corr = __expf(m_prev[i] - mn);
            float rs = 0.0f;
            #pragma unroll
            for (int j = 0; j < 4; j++) {
                s[i][j] = __expf(s[i][j] - mn);
                rs += s[i][j];
            }
            #pragma unroll
            for (int off = 1; off < 16; off <<= 1)
                rs += __shfl_xor_sync(0xffffffffu, rs, off);
            l[i] = l[i] * corr + rs;
            #pragma unroll
            for (int j = 0; j < 4; j++) o[i][j] *= corr;
            m_prev[i] = mn;
        }

        __syncthreads();   // all S reads of KP done before overwriting with P

        // Store P transposed ([key][qrow]), same swizzle scheme
        #pragma unroll
        for (int j = 0; j < 4; j++) {
            int keyr = tx * 4 + j;
            #pragma unroll
            for (int i = 0; i < 4; i++)
                KP[keyr][4 * (ty ^ (keyr & 15)) + i] = s[i][j];
        }
        __syncthreads();

        // O += P * V  (rows ty*4+i = qrows, cols tx*4+j = d)
        #pragma unroll 16
        for (int kk = 0; kk < 64; kk++) {
            float4 af = *(const float4*)&KP[kk][4 * (ty ^ (kk & 15))];
            float4 bf = *(const float4*)&Vs[kk][tx * 4];
            float* ap = (float*)&af;
            float* bp = (float*)&bf;
            #pragma unroll
            for (int i = 0; i < 4; i++)
                #pragma unroll
                for (int j = 0; j < 4; j++)
                    o[i][j] = fmaf(ap[i], bp[j], o[i][j]);
        }
        __syncthreads();   // before next iteration overwrites KP / Vs
    }

    // Normalize and write to g_mh [B,N,H*DH]
    #pragma unroll
    for (int i = 0; i < 4; i++) {
        float inv = 1.0f / l[i];
        int n = nt * 64 + ty * 4 + i;
        float v[4];
        #pragma unroll
        for (int j = 0; j < 4; j++) v[j] = o[i][j] * inv;
        *(float4*)&g_mh[(b * N_ + n) * HD_ + h * DH_ + tx * 4] = *(float4*)&v[0];
    }
}

// ---------------------------------------------------------------------------
// Launch
// ---------------------------------------------------------------------------
extern "C" void kernel_launch(void* const* d_in, const int* in_sizes, int n_in,
                              void* d_out, int out_size)
{
    const float* query = (const float*)d_in[0];
    const float* key   = (const float*)d_in[1];
    const float* value = (const float*)d_in[2];
    const float* wq    = (const float*)d_in[3];
    const float* wk    = (const float*)d_in[4];
    const float* wv    = (const float*)d_in[5];
    const float* wp    = (const float*)d_in[6];
    const float* bq    = (const float*)d_in[7];
    const float* bk    = (const float*)d_in[8];
    const float* bv    = (const float*)d_in[9];
    const float* pb    = (const float*)d_in[10];
    float* out = (float*)d_out;
    (void)in_sizes; (void)n_in; (void)out_size;

    repack_kernel<<<(3 * DM_ * HD_ + 255) / 256, 256>>>(wq, wk, wv, bq, bk, bv);

    dim3 gqkv(HD_ / 128, (B_ * N_) / 128, 3);
    gemm_qkv_kernel<<<gqkv, 256>>>(query, key, value);

    dim3 gfl(N_ / 64, H_, B_);
    flash_kernel<<<gfl, 256>>>();

    dim3 gpr(HD_ / 128, (B_ * N_) / 128);
    gemm_proj_kernel<<<gpr, 256>>>(wp, pb, out);
}

// round 2
// speedup vs baseline: 1.2308x; 1.2308x over previous
#include <cuda_runtime.h>
#include <cuda_bf16.h>

using u32 = unsigned int;

constexpr int B_  = 4;
constexpr int N_  = 2048;
constexpr int DM_ = 512;
constexpr int H_  = 8;
constexpr int DH_ = 64;
constexpr int HD_ = 512;          // H*DH == DO
constexpr int ROWS_ = B_ * N_;    // 8192

// ---------------------------------------------------------------------------
// Scratch (device globals; no runtime allocation). All bf16 hi/lo split pairs.
// ---------------------------------------------------------------------------
__device__ __align__(16) __nv_bfloat16 g_act_h[3][ROWS_ * DM_];
__device__ __align__(16) __nv_bfloat16 g_act_l[3][ROWS_ * DM_];
__device__ __align__(16) __nv_bfloat16 g_wt_h[3][HD_ * DM_];   // qkv weights, transposed [n][k]
__device__ __align__(16) __nv_bfloat16 g_wt_l[3][HD_ * DM_];
__device__ __align__(16) __nv_bfloat16 g_wpt_h[HD_ * HD_];     // proj weight, transposed [o][hd]
__device__ __align__(16) __nv_bfloat16 g_wpt_l[HD_ * HD_];
__device__ float g_bias[3][HD_];
__device__ __align__(16) __nv_bfloat16 g_qkv_h[3][B_ * H_ * N_ * DH_];  // [B,H,seq,DH]
__device__ __align__(16) __nv_bfloat16 g_qkv_l[3][B_ * H_ * N_ * DH_];
__device__ __align__(16) __nv_bfloat16 g_mh_h[ROWS_ * HD_];    // [B*N, H*DH]
__device__ __align__(16) __nv_bfloat16 g_mh_l[ROWS_ * HD_];

// ---------------------------------------------------------------------------
// Helpers
// ---------------------------------------------------------------------------
// Split two floats into bf16 hi/lo pairs packed as u32 words (low half = first).
__device__ __forceinline__ void split_pack(float x, float y, u32& hi, u32& lo)
{
    __nv_bfloat16 hx = __float2bfloat16(x), hy = __float2bfloat16(y);
    float rx = x - __bfloat162float(hx);
    float ry = y - __bfloat162float(hy);
    __nv_bfloat16 lx = __float2bfloat16(rx), ly = __float2bfloat16(ry);
    hi = (u32)*(unsigned short*)&hx | ((u32)*(unsigned short*)&hy << 16);
    lo = (u32)*(unsigned short*)&lx | ((u32)*(unsigned short*)&ly << 16);
}

__device__ __forceinline__ void mma_bf16(float& c0, float& c1, float& c2, float& c3,
                                         const u32 a[4], const u32 b[2])
{
    asm volatile(
        "mma.sync.aligned.m16n8k16.row.col.f32.bf16.bf16.f32 "
        "{%0,%1,%2,%3},{%4,%5,%6,%7},{%8,%9},{%0,%1,%2,%3};\n"
        : "+f"(c0), "+f"(c1), "+f"(c2), "+f"(c3)
        : "r"(a[0]), "r"(a[1]), "r"(a[2]), "r"(a[3]), "r"(b[0]), "r"(b[1]));
}

// Tiles in smem: rows x 64 bf16 = rows x 32 words. XOR swizzle on 4-word groups:
// physical word = r*32 + ((grp ^ (r&7))<<2) + (w&3). Conflict-free fragment loads.
template <int NTHR>
__device__ __forceinline__ void load_tile(u32* s, const __nv_bfloat16* g,
                                          int gstride, int rows, int tid)
{
    for (int idx = tid; idx < rows * 8; idx += NTHR) {
        int r = idx >> 3, grp = idx & 7;
        uint4 v = *(const uint4*)(g + r * gstride + grp * 8);
        *(uint4*)(s + r * 32 + ((grp ^ (r & 7)) << 2)) = v;
    }
}

// A fragment (m16 x k16), atom rows start at r0 (multiple of 16), k16 chunk kk.
__device__ __forceinline__ void load_afrag(u32 a[4], const u32* s, int r0, int kk,
                                           int g, int t)
{
    int ra = r0 + g, rb = ra + 8;
    a[0] = s[ra * 32 + (((2 * kk)     ^ (ra & 7)) << 2) + t];
    a[1] = s[rb * 32 + (((2 * kk)     ^ (rb & 7)) << 2) + t];
    a[2] = s[ra * 32 + (((2 * kk + 1) ^ (ra & 7)) << 2) + t];
    a[3] = s[rb * 32 + (((2 * kk + 1) ^ (rb & 7)) << 2) + t];
}

// B fragment (k16 x n8) from a tile stored [n][k] (pairs along k contiguous).
__device__ __forceinline__ void load_bfrag(u32 b[2], const u32* s, int r0, int kk,
                                           int g, int t)
{
    int r = r0 + g;
    b[0] = s[r * 32 + (((2 * kk)     ^ (r & 7)) << 2) + t];
    b[1] = s[r * 32 + (((2 * kk + 1) ^ (r & 7)) << 2) + t];
}

// B fragment element pair for V stored [key][dh]: element (k=key, n=dh) pairs
// along key = two 16-bit loads from adjacent key rows (same word/broadcast class).
__device__ __forceinline__ u32 ldV(const u32* s, int k, int j, int g)
{
    const unsigned short* p = (const unsigned short*)s;
    unsigned short v0 = p[(k * 32       + ((j ^ (k & 7))       << 2) + (g >> 1)) * 2 + (g & 1)];
    unsigned short v1 = p[((k + 1) * 32 + ((j ^ ((k + 1) & 7)) << 2) + (g >> 1)) * 2 + (g & 1)];
    return (u32)v0 | ((u32)v1 << 16);
}

// ---------------------------------------------------------------------------
// Conversion kernels (run once per launch, tiny vs GEMM cost)
// ---------------------------------------------------------------------------
__global__ void conv_acts(const float* __restrict__ q, const float* __restrict__ k,
                          const float* __restrict__ v)
{
    int gid = blockIdx.x * 256 + threadIdx.x;
    const int per = ROWS_ * DM_ / 4;
    if (gid >= 3 * per) return;
    int sel = gid / per, off = gid - sel * per;
    const float* src = (sel == 0) ? q : (sel == 1 ? k : v);
    float4 x = ((const float4*)src)[off];
    u32 h0, l0, h1, l1;
    split_pack(x.x, x.y, h0, l0);
    split_pack(x.z, x.w, h1, l1);
    ((uint2*)g_act_h[sel])[off] = make_uint2(h0, h1);
    ((uint2*)g_act_l[sel])[off] = make_uint2(l0, l1);
}

__global__ void conv_w(const float* __restrict__ wq, const float* __restrict__ wk,
                       const float* __restrict__ wv, const float* __restrict__ wp,
                       const float* __restrict__ bq, const float* __restrict__ bk,
                       const float* __restrict__ bv)
{
    int gid = blockIdx.x * 256 + threadIdx.x;
    const int perw = HD_ * DM_ / 4;   // 65536 quads per qkv weight
    const int perp = HD_ * HD_ / 4;   // 65536 quads for proj weight
    if (gid < 3 * perw) {
        int sel = gid / perw, rem = gid - sel * perw;
        int n = rem / (DM_ / 4), kq = rem - n * (DM_ / 4), k = kq * 4;
        const float* w = (sel == 0) ? wq : (sel == 1 ? wk : wv);
        int h = n >> 6, o = n & 63;
        const float* base = w + h * DM_ * DH_ + o;   // [h][i][o], stride DH over i
        float x0 = base[(k + 0) * DH_], x1 = base[(k + 1) * DH_];
        float x2 = base[(k + 2) * DH_], x3 = base[(k + 3) * DH_];
        u32 h0, l0, h1, l1;
        split_pack(x0, x1, h0, l0);
        split_pack(x2, x3, h1, l1);
        ((uint2*)g_wt_h[sel])[rem] = make_uint2(h0, h1);
        ((uint2*)g_wt_l[sel])[rem] = make_uint2(l0, l1);
    } else if (gid < 3 * perw + perp) {
        int rem = gid - 3 * perw;
        int n = rem / (HD_ / 4), kq = rem - n * (HD_ / 4), k = kq * 4;
        // wp flat [HD_][HD_] = [h*64+d][o]; transposed store [o][hd]
        float x0 = wp[(k + 0) * HD_ + n], x1 = wp[(k + 1) * HD_ + n];
        float x2 = wp[(k + 2) * HD_ + n], x3 = wp[(k + 3) * HD_ + n];
        u32 h0, l0, h1, l1;
        split_pack(x0, x1, h0, l0);
        split_pack(x2, x3, h1, l1);
        ((uint2*)g_wpt_h)[rem] = make_uint2(h0, h1);
        ((uint2*)g_wpt_l)[rem] = make_uint2(l0, l1);
    } else {
        int t = gid - 3 * perw - perp;
        if (t < 3 * HD_) {
            int sel = t / HD_, j = t - sel * HD_;
            const float* bb = (sel == 0) ? bq : (sel == 1 ? bk : bv);
            g_bias[sel][j] = bb[j];
        }
    }
}

// ---------------------------------------------------------------------------
// Tensor-core GEMM: C[8192 x 512] = A[8192 x 512] * W^T-stored[512 x 512]
// Block tile M=64 x N=128, 8 warps (4m x 2n), warp tile m16 x n64, BK=64.
// 3 MMAs per atom for the bf16 hi/lo split.
// MODE 0: qkv (blockIdx.z = sel) -> bias (+scale for q) -> split-store [B,H,seq,DH]
// MODE 1: proj -> + projection_bias -> fp32 out
// ---------------------------------------------------------------------------
template <int MODE>
__global__ __launch_bounds__(256) void gemm_kernel(const float* __restrict__ pbias,
                                                   float* __restrict__ out)
{
    __shared__ u32 sAh[64 * 32], sAl[64 * 32], sBh[128 * 32], sBl[128 * 32];

    int tid = threadIdx.x, lane = tid & 31, wid = tid >> 5;
    int g = lane >> 2, t = lane & 3;
    int wm = wid & 3, wn = wid >> 2;
    int m0 = blockIdx.y * 64, n0 = blockIdx.x * 128;
    int sel = (MODE == 0) ? blockIdx.z : 0;

    const __nv_bfloat16 *Ah, *Al, *Bh, *Bl;
    if (MODE == 0) { Ah = g_act_h[sel]; Al = g_act_l[sel]; Bh = g_wt_h[sel]; Bl = g_wt_l[sel]; }
    else           { Ah = g_mh_h;       Al = g_mh_l;       Bh = g_wpt_h;     Bl = g_wpt_l;     }

    float acc[8][4] = {};

    for (int k0 = 0; k0 < DM_; k0 += 64) {
        load_tile<256>(sAh, Ah + m0 * DM_ + k0, DM_, 64, tid);
        load_tile<256>(sAl, Al + m0 * DM_ + k0, DM_, 64, tid);
        load_tile<256>(sBh, Bh + n0 * DM_ + k0, DM_, 128, tid);
        load_tile<256>(sBl, Bl + n0 * DM_ + k0, DM_, 128, tid);
        __syncthreads();
        #pragma unroll
        for (int kk = 0; kk < 4; kk++) {
            u32 ah[4], al[4];
            load_afrag(ah, sAh, wm * 16, kk, g, t);
            load_afrag(al, sAl, wm * 16, kk, g, t);
            #pragma unroll
            for (int j = 0; j < 8; j++) {
                u32 bh[2], bl[2];
                load_bfrag(bh, sBh, wn * 64 + j * 8, kk, g, t);
                load_bfrag(bl, sBl, wn * 64 + j * 8, kk, g, t);
                mma_bf16(acc[j][0], acc[j][1], acc[j][2], acc[j][3], ah, bh);
                mma_bf16(acc[j][0], acc[j][1], acc[j][2], acc[j][3], ah, bl);
                mma_bf16(acc[j][0], acc[j][1], acc[j][2], acc[j][3], al, bh);
            }
        }
        __syncthreads();
    }

    #pragma unroll
    for (int j = 0; j < 8; j++) {
        int gc = n0 + wn * 64 + j * 8 + 2 * t;
        #pragma unroll
        for (int half = 0; half < 2; half++) {
            int gr = m0 + wm * 16 + g + 8 * half;
            float v0 = acc[j][2 * half], v1 = acc[j][2 * half + 1];
            if (MODE == 0) {
                float sc = (sel == 0) ? 0.125f : 1.0f;
                v0 = (v0 + g_bias[sel][gc]) * sc;
                v1 = (v1 + g_bias[sel][gc + 1]) * sc;
                int b = gr >> 11, n = gr & 2047, h = gc >> 6, d = gc & 63;
                int idx = (((b * H_ + h) * N_ + n) * DH_) + d;
                u32 hw, lw;
                split_pack(v0, v1, hw, lw);
                *(u32*)&g_qkv_h[sel][idx] = hw;
                *(u32*)&g_qkv_l[sel][idx] = lw;
            } else {
                v0 += pbias[gc];
                v1 += pbias[gc + 1];
                *(float2*)&out[gr * HD_ + gc] = make_float2(v0, v1);
            }
        }
    }
}

// ---------------------------------------------------------------------------
// Flash attention on tensor cores. Block = 64 q-rows of one (b,h); 4 warps,
// warp = m16 x n64. P stays in registers (S accumulator layout == A fragment
// layout for PV). Online softmax is fully warp-local per row.
// ---------------------------------------------------------------------------
__global__ __launch_bounds__(128) void flash_kernel()
{
    __shared__ u32 sQh[64 * 32], sQl[64 * 32];
    __shared__ u32 sKh[64 * 32], sKl[64 * 32];
    __shared__ u32 sVh[64 * 32], sVl[64 * 32];

    int tid = threadIdx.x, lane = tid & 31, wid = tid >> 5;
    int g = lane >> 2, t = lane & 3;
    int nt = blockIdx.x, h = blockIdx.y, b = blockIdx.z;

    int qoff  = ((b * H_ + h) * N_ + nt * 64) * DH_;
    int kvoff = (b * H_ + h) * N_ * DH_;

    load_tile<128>(sQh, g_qkv_h[0] + qoff, DH_, 64, tid);
    load_tile<128>(sQl, g_qkv_l[0] + qoff, DH_, 64, tid);

    float o[8][4] = {};
    float mprev[2] = {-1e30f, -1e30f};
    float l[2] = {0.f, 0.f};

    for (int mt = 0; mt < N_; mt += 64) {
        load_tile<128>(sKh, g_qkv_h[1] + kvoff + mt * DH_, DH_, 64, tid);
        load_tile<128>(sKl, g_qkv_l[1] + kvoff + mt * DH_, DH_, 64, tid);
        load_tile<128>(sVh, g_qkv_h[2] + kvoff + mt * DH_, DH_, 64, tid);
        load_tile<128>(sVl, g_qkv_l[2] + kvoff + mt * DH_, DH_, 64, tid);
        __syncthreads();

        // S = Q * K^T  (64 keys this tile)
        float s[8][4] = {};
        #pragma unroll
        for (int kk = 0; kk < 4; kk++) {
            u32 ah[4], al[4];
            load_afrag(ah, sQh, wid * 16, kk, g, t);
            load_afrag(al, sQl, wid * 16, kk, g, t);
            #pragma unroll
            for (int j = 0; j < 8; j++) {
                u32 bh[2], bl[2];
                load_bfrag(bh, sKh, j * 8, kk, g, t);
                load_bfrag(bl, sKl, j * 8, kk, g, t);
                mma_bf16(s[j][0], s[j][1], s[j][2], s[j][3], ah, bh);
                mma_bf16(s[j][0], s[j][1], s[j][2], s[j][3], ah, bl);
                mma_bf16(s[j][0], s[j][1], s[j][2], s[j][3], al, bh);
            }
        }

        // Online softmax; rows (g) and (g+8) per thread, spread over 4 lanes
        #pragma unroll
        for (int half = 0; half < 2; half++) {
            float mx = -1e30f;
            #pragma unroll
            for (int j = 0; j < 8; j++)
                mx = fmaxf(mx, fmaxf(s[j][2 * half], s[j][2 * half + 1]));
            mx = fmaxf(mx, __shfl_xor_sync(0xffffffffu, mx, 1));
            mx = fmaxf(mx, __shfl_xor_sync(0xffffffffu, mx, 2));
            float mnew = fmaxf(mprev[half], mx);
            float corr = __expf(mprev[half] - mnew);
            float rs = 0.f;
            #pragma unroll
            for (int j = 0; j < 8; j++) {
                s[j][2 * half]     = __expf(s[j][2 * half]     - mnew);
                s[j][2 * half + 1] = __expf(s[j][2 * half + 1] - mnew);
                rs += s[j][2 * half] + s[j][2 * half + 1];
            }
            rs += __shfl_xor_sync(0xffffffffu, rs, 1);
            rs += __shfl_xor_sync(0xffffffffu, rs, 2);
            l[half] = l[half] * corr + rs;
            mprev[half] = mnew;
            #pragma unroll
            for (int j = 0; j < 8; j++) {
                o[j][2 * half]     *= corr;
                o[j][2 * half + 1] *= corr;
            }
        }

        // O += P * V ; P converted from S regs directly into A fragments
        #pragma unroll
        for (int ka = 0; ka < 4; ka++) {
            u32 ah[4], al[4];
            split_pack(s[2 * ka][0],     s[2 * ka][1],     ah[0], al[0]);
            split_pack(s[2 * ka][2],     s[2 * ka][3],     ah[1], al[1]);
            split_pack(s[2 * ka + 1][0], s[2 * ka + 1][1], ah[2], al[2]);
            split_pack(s[2 * ka + 1][2], s[2 * ka + 1][3], ah[3], al[3]);
            int kb = ka * 16 + 2 * t;
            #pragma unroll
            for (int j = 0; j < 8; j++) {
                u32 bh[2], bl[2];
                bh[0] = ldV(sVh, kb, j, g);
                bh[1] = ldV(sVh, kb + 8, j, g);
                bl[0] = ldV(sVl, kb, j, g);
                bl[1] = ldV(sVl, kb + 8, j, g);
                mma_bf16(o[j][0], o[j][1], o[j][2], o[j][3], ah, bh);
                mma_bf16(o[j][0], o[j][1], o[j][2], o[j][3], ah, bl);
                mma_bf16(o[j][0], o[j][1], o[j][2], o[j][3], al, bh);
            }
        }
        __syncthreads();
    }

    // Normalize and split-store to g_mh [B*N][H*DH]
    #pragma unroll
    for (int half = 0; half < 2; half++) {
        float inv = 1.0f / l[half];
        int n = nt * 64 + wid * 16 + g + 8 * half;
        int row = b * N_ + n;
        #pragma unroll
        for (int j = 0; j < 8; j++) {
            int col = h * DH_ + j * 8 + 2 * t;
            u32 hw, lw;
            split_pack(o[j][2 * half] * inv, o[j][2 * half + 1] * inv, hw, lw);
            *(u32*)&g_mh_h[row * HD_ + col] = hw;
            *(u32*)&g_mh_l[row * HD_ + col] = lw;
        }
    }
}

// ---------------------------------------------------------------------------
// Launch
// ---------------------------------------------------------------------------
extern "C" void kernel_launch(void* const* d_in, const int* in_sizes, int n_in,
                              void* d_out, int out_size)
{
    const float* query = (const float*)d_in[0];
    const float* key   = (const float*)d_in[1];
    const float* value = (const float*)d_in[2];
    const float* wq    = (const float*)d_in[3];
    const float* wk    = (const float*)d_in[4];
    const float* wv    = (const float*)d_in[5];
    const float* wp    = (const float*)d_in[6];
    const float* bq    = (const float*)d_in[7];
    const float* bk    = (const float*)d_in[8];
    const float* bv    = (const float*)d_in[9];
    const float* pb    = (const float*)d_in[10];
    float* out = (float*)d_out;
    (void)in_sizes; (void)n_in; (void)out_size;

    int acts_threads = 3 * (ROWS_ * DM_ / 4);
    conv_acts<<<(acts_threads + 255) / 256, 256>>>(query, key, value);

    int w_threads = 3 * (HD_ * DM_ / 4) + (HD_ * HD_ / 4) + 3 * HD_;
    conv_w<<<(w_threads + 255) / 256, 256>>>(wq, wk, wv, wp, bq, bk, bv);

    dim3 gq(HD_ / 128, ROWS_ / 64, 3);
    gemm_kernel<0><<<gq, 256>>>(nullptr, nullptr);

    dim3 gf(N_ / 64, H_, B_);
    flash_kernel<<<gf, 128>>>();

    dim3 gp(HD_ / 128, ROWS_ / 64);
    gemm_kernel<1><<<gp, 256>>>(pb, out);
}

// round 3
// speedup vs baseline: 2.8362x; 2.3045x over previous
#include <cuda_runtime.h>
#include <cuda_bf16.h>

using u32 = unsigned int;
using u16 = unsigned short;

constexpr int B_  = 4;
constexpr int N_  = 2048;
constexpr int DM_ = 512;
constexpr int H_  = 8;
constexpr int DH_ = 64;
constexpr int HD_ = 512;          // H*DH == DO
constexpr int ROWS_ = B_ * N_;    // 8192

// ---------------------------------------------------------------------------
// Scratch (device globals; no runtime allocation). bf16 hi/lo split pairs.
// ---------------------------------------------------------------------------
__device__ __align__(16) __nv_bfloat16 g_act_h[3][ROWS_ * DM_];
__device__ __align__(16) __nv_bfloat16 g_act_l[3][ROWS_ * DM_];
__device__ __align__(16) __nv_bfloat16 g_wt_h[3][HD_ * DM_];   // qkv weights [n][k]
__device__ __align__(16) __nv_bfloat16 g_wt_l[3][HD_ * DM_];
__device__ __align__(16) __nv_bfloat16 g_wpt_h[HD_ * HD_];     // proj weight [o][hd]
__device__ __align__(16) __nv_bfloat16 g_wpt_l[HD_ * HD_];
__device__ float g_bias[3][HD_];
__device__ __align__(16) __nv_bfloat16 g_qkv_h[2][B_ * H_ * N_ * DH_];  // Q,K [B,H,seq,DH]
__device__ __align__(16) __nv_bfloat16 g_qkv_l[2][B_ * H_ * N_ * DH_];
__device__ __align__(16) __nv_bfloat16 g_vt_h[B_ * H_ * DH_ * N_];      // V^T [B,H,DH,seq]
__device__ __align__(16) __nv_bfloat16 g_vt_l[B_ * H_ * DH_ * N_];
__device__ __align__(16) __nv_bfloat16 g_mh_h[ROWS_ * HD_];    // [B*N, H*DH]
__device__ __align__(16) __nv_bfloat16 g_mh_l[ROWS_ * HD_];

// ---------------------------------------------------------------------------
// Helpers
// ---------------------------------------------------------------------------
__device__ __forceinline__ void split_pack(float x, float y, u32& hi, u32& lo)
{
    __nv_bfloat16 hx = __float2bfloat16(x), hy = __float2bfloat16(y);
    float rx = x - __bfloat162float(hx);
    float ry = y - __bfloat162float(hy);
    __nv_bfloat16 lx = __float2bfloat16(rx), ly = __float2bfloat16(ry);
    hi = (u32)*(u16*)&hx | ((u32)*(u16*)&hy << 16);
    lo = (u32)*(u16*)&lx | ((u32)*(u16*)&ly << 16);
}

__device__ __forceinline__ void split1(float x, u16& h, u16& l)
{
    __nv_bfloat16 hh = __float2bfloat16(x);
    float r = x - __bfloat162float(hh);
    __nv_bfloat16 ll = __float2bfloat16(r);
    h = *(u16*)&hh; l = *(u16*)&ll;
}

__device__ __forceinline__ void mma_bf16(float& c0, float& c1, float& c2, float& c3,
                                         const u32 a[4], const u32 b[2])
{
    asm volatile(
        "mma.sync.aligned.m16n8k16.row.col.f32.bf16.bf16.f32 "
        "{%0,%1,%2,%3},{%4,%5,%6,%7},{%8,%9},{%0,%1,%2,%3};\n"
        : "+f"(c0), "+f"(c1), "+f"(c2), "+f"(c3)
        : "r"(a[0]), "r"(a[1]), "r"(a[2]), "r"(a[3]), "r"(b[0]), "r"(b[1]));
}

__device__ __forceinline__ u32 smem_u32(const void* p)
{
    return (u32)__cvta_generic_to_shared(p);
}
__device__ __forceinline__ void cp16(u32 dst, const void* src)
{
    asm volatile("cp.async.cg.shared.global [%0], [%1], 16;\n" :: "r"(dst), "l"(src));
}
__device__ __forceinline__ void cp_commit()
{
    asm volatile("cp.async.commit_group;\n" ::);
}
template <int NPend>
__device__ __forceinline__ void cp_wait()
{
    asm volatile("cp.async.wait_group %0;\n" :: "n"(NPend));
}

// Smem tiles: rows x 32 u32 (64 bf16). XOR swizzle: word = r*32 + ((grp^(r&7))<<2)+w.
// A fragment (m16 x k16), atom rows at r0, chunk kk: kk 0..3 index 8-bf16 groups 2kk,2kk+1.
__device__ __forceinline__ void load_afrag(u32 a[4], const u32* s, int r0, int kk,
                                           int g, int t)
{
    int ra = r0 + g, rb = ra + 8;
    a[0] = s[ra * 32 + (((2 * kk)     ^ (ra & 7)) << 2) + t];
    a[1] = s[rb * 32 + (((2 * kk)     ^ (rb & 7)) << 2) + t];
    a[2] = s[ra * 32 + (((2 * kk + 1) ^ (ra & 7)) << 2) + t];
    a[3] = s[rb * 32 + (((2 * kk + 1) ^ (rb & 7)) << 2) + t];
}
// B fragment (k16 x n8) from tile stored [n][k].
__device__ __forceinline__ void load_bfrag(u32 b[2], const u32* s, int r0, int kk,
                                           int g, int t)
{
    int r = r0 + g;
    b[0] = s[r * 32 + (((2 * kk)     ^ (r & 7)) << 2) + t];
    b[1] = s[r * 32 + (((2 * kk + 1) ^ (r & 7)) << 2) + t];
}

// Async-fill a 64-row x 64-bf16 tile (512 x 16B chunks) with the XOR swizzle.
__device__ __forceinline__ void cpa_tile64(u32* s, const __nv_bfloat16* g,
                                           int gstride, int tid)
{
    #pragma unroll
    for (int it = 0; it < 2; it++) {
        int idx = tid + it * 256;
        int r = idx >> 3, grp = idx & 7;
        cp16(smem_u32(s + r * 32 + ((grp ^ (r & 7)) << 2)), g + r * gstride + grp * 8);
    }
}

// ---------------------------------------------------------------------------
// Conversion kernels
// ---------------------------------------------------------------------------
__global__ void conv_acts(const float* __restrict__ q, const float* __restrict__ k,
                          const float* __restrict__ v)
{
    int gid = blockIdx.x * 256 + threadIdx.x;
    const int per = ROWS_ * DM_ / 4;
    if (gid >= 3 * per) return;
    int sel = gid / per, off = gid - sel * per;
    const float* src = (sel == 0) ? q : (sel == 1 ? k : v);
    float4 x = ((const float4*)src)[off];
    u32 h0, l0, h1, l1;
    split_pack(x.x, x.y, h0, l0);
    split_pack(x.z, x.w, h1, l1);
    ((uint2*)g_act_h[sel])[off] = make_uint2(h0, h1);
    ((uint2*)g_act_l[sel])[off] = make_uint2(l0, l1);
}

__global__ void conv_w(const float* __restrict__ wq, const float* __restrict__ wk,
                       const float* __restrict__ wv, const float* __restrict__ wp,
                       const float* __restrict__ bq, const float* __restrict__ bk,
                       const float* __restrict__ bv)
{
    int gid = blockIdx.x * 256 + threadIdx.x;
    const int perw = HD_ * DM_ / 4;
    const int perp = HD_ * HD_ / 4;
    if (gid < 3 * perw) {
        int sel = gid / perw, rem = gid - sel * perw;
        int n = rem / (DM_ / 4), kq = rem - n * (DM_ / 4), k = kq * 4;
        const float* w = (sel == 0) ? wq : (sel == 1 ? wk : wv);
        int h = n >> 6, o = n & 63;
        const float* base = w + h * DM_ * DH_ + o;
        float x0 = base[(k + 0) * DH_], x1 = base[(k + 1) * DH_];
        float x2 = base[(k + 2) * DH_], x3 = base[(k + 3) * DH_];
        u32 h0, l0, h1, l1;
        split_pack(x0, x1, h0, l0);
        split_pack(x2, x3, h1, l1);
        ((uint2*)g_wt_h[sel])[rem] = make_uint2(h0, h1);
        ((uint2*)g_wt_l[sel])[rem] = make_uint2(l0, l1);
    } else if (gid < 3 * perw + perp) {
        int rem = gid - 3 * perw;
        int n = rem / (HD_ / 4), kq = rem - n * (HD_ / 4), k = kq * 4;
        float x0 = wp[(k + 0) * HD_ + n], x1 = wp[(k + 1) * HD_ + n];
        float x2 = wp[(k + 2) * HD_ + n], x3 = wp[(k + 3) * HD_ + n];
        u32 h0, l0, h1, l1;
        split_pack(x0, x1, h0, l0);
        split_pack(x2, x3, h1, l1);
        ((uint2*)g_wpt_h)[rem] = make_uint2(h0, h1);
        ((uint2*)g_wpt_l)[rem] = make_uint2(l0, l1);
    } else {
        int t = gid - 3 * perw - perp;
        if (t < 3 * HD_) {
            int sel = t / HD_, j = t - sel * HD_;
            const float* bb = (sel == 0) ? bq : (sel == 1 ? bk : bv);
            g_bias[sel][j] = bb[j];
        }
    }
}

// ---------------------------------------------------------------------------
// GEMM: C[8192x512] = A[8192x512] * B^T-stored. Block 128m x 64n, BK=32,
// hi/lo interleaved per smem row (words 0..15 = hi k0..31, 16..31 = lo),
// double-buffered cp.async, 8 warps (4m x 2n), warp tile m32 x n32.
// MODE 0: qkv (z=sel); Q,K -> [B,H,seq,DH]; V -> transposed [B,H,DH,seq].
// MODE 1: proj + bias -> fp32 out.
// ---------------------------------------------------------------------------
__device__ __forceinline__ void fill_stage(u32* sa, u32* sb,
                                           const __nv_bfloat16* Ah, const __nv_bfloat16* Al,
                                           const __nv_bfloat16* Bh, const __nv_bfloat16* Bl,
                                           int k0, int tid)
{
    #pragma unroll
    for (int it = 0; it < 4; it++) {
        int idx = tid + it * 256;
        int r = idx >> 3, grp = idx & 7;
        const __nv_bfloat16* src = (grp < 4) ? Ah + r * DM_ + k0 + grp * 8
                                             : Al + r * DM_ + k0 + (grp & 3) * 8;
        cp16(smem_u32(sa + r * 32 + ((grp ^ (r & 7)) << 2)), src);
    }
    #pragma unroll
    for (int it = 0; it < 2; it++) {
        int idx = tid + it * 256;
        int r = idx >> 3, grp = idx & 7;
        const __nv_bfloat16* src = (grp < 4) ? Bh + r * DM_ + k0 + grp * 8
                                             : Bl + r * DM_ + k0 + (grp & 3) * 8;
        cp16(smem_u32(sb + r * 32 + ((grp ^ (r & 7)) << 2)), src);
    }
}

template <int MODE>
__global__ __launch_bounds__(256, 2) void gemm_kernel(const float* __restrict__ pbias,
                                                      float* __restrict__ out)
{
    __shared__ u32 sA[2][128 * 32];
    __shared__ u32 sB[2][64 * 32];

    int tid = threadIdx.x, lane = tid & 31, wid = tid >> 5;
    int g = lane >> 2, t = lane & 3;
    int wm = wid & 3, wn = wid >> 2;
    int n0 = blockIdx.x * 64, m0 = blockIdx.y * 128;
    int sel = (MODE == 0) ? blockIdx.z : 0;

    const __nv_bfloat16 *Ah, *Al, *Bh, *Bl;
    if (MODE == 0) { Ah = g_act_h[sel]; Al = g_act_l[sel]; Bh = g_wt_h[sel]; Bl = g_wt_l[sel]; }
    else           { Ah = g_mh_h;       Al = g_mh_l;       Bh = g_wpt_h;     Bl = g_wpt_l;     }
    Ah += m0 * DM_; Al += m0 * DM_;
    Bh += n0 * DM_; Bl += n0 * DM_;

    fill_stage(sA[0], sB[0], Ah, Al, Bh, Bl, 0, tid);  cp_commit();
    fill_stage(sA[1], sB[1], Ah, Al, Bh, Bl, 32, tid); cp_commit();

    float acc[2][4][4] = {};
    cp_wait<1>();
    __syncthreads();

    for (int ks = 0; ks < 16; ks++) {
        int cur = ks & 1;
        #pragma unroll
        for (int c = 0; c < 2; c++) {
            u32 a_h[2][4], a_l[2][4];
            load_afrag(a_h[0], sA[cur], wm * 32,      c,     g, t);
            load_afrag(a_h[1], sA[cur], wm * 32 + 16, c,     g, t);
            load_afrag(a_l[0], sA[cur], wm * 32,      c + 2, g, t);
            load_afrag(a_l[1], sA[cur], wm * 32 + 16, c + 2, g, t);
            #pragma unroll
            for (int na = 0; na < 4; na++) {
                u32 b_h[2], b_l[2];
                load_bfrag(b_h, sB[cur], wn * 32 + na * 8, c,     g, t);
                load_bfrag(b_l, sB[cur], wn * 32 + na * 8, c + 2, g, t);
                #pragma unroll
                for (int ma = 0; ma < 2; ma++) {
                    mma_bf16(acc[ma][na][0], acc[ma][na][1], acc[ma][na][2], acc[ma][na][3], a_h[ma], b_h);
                    mma_bf16(acc[ma][na][0], acc[ma][na][1], acc[ma][na][2], acc[ma][na][3], a_h[ma], b_l);
                    mma_bf16(acc[ma][na][0], acc[ma][na][1], acc[ma][na][2], acc[ma][na][3], a_l[ma], b_h);
                }
            }
        }
        __syncthreads();
        int kn = (ks + 2 < 16) ? ks + 2 : 15;
        fill_stage(sA[cur], sB[cur], Ah, Al, Bh, Bl, kn * 32, tid);
        cp_commit();
        cp_wait<1>();
        __syncthreads();
    }
    cp_wait<0>();

    #pragma unroll
    for (int ma = 0; ma < 2; ma++) {
        #pragma unroll
        for (int na = 0; na < 4; na++) {
            int gc = n0 + wn * 32 + na * 8 + 2 * t;
            #pragma unroll
            for (int half = 0; half < 2; half++) {
                int gr = m0 + wm * 32 + ma * 16 + g + 8 * half;
                float v0 = acc[ma][na][2 * half], v1 = acc[ma][na][2 * half + 1];
                if (MODE == 0) {
                    v0 += g_bias[sel][gc];
                    v1 += g_bias[sel][gc + 1];
                    if (sel == 0) { v0 *= 0.125f; v1 *= 0.125f; }
                    int b = gr >> 11, n = gr & 2047, hh = gc >> 6, d = gc & 63;
                    if (sel < 2) {
                        int idx = (((b * H_ + hh) * N_ + n) * DH_) + d;
                        u32 hw, lw;
                        split_pack(v0, v1, hw, lw);
                        *(u32*)&g_qkv_h[sel][idx] = hw;
                        *(u32*)&g_qkv_l[sel][idx] = lw;
                    } else {   // V: store transposed [B,H,DH,N]
                        int base = (((b * H_ + hh) * DH_) + d) * N_ + n;
                        u16 h0, l0, h1, l1;
                        split1(v0, h0, l0);
                        split1(v1, h1, l1);
                        *(u16*)&g_vt_h[base]      = h0;
                        *(u16*)&g_vt_l[base]      = l0;
                        *(u16*)&g_vt_h[base + N_] = h1;
                        *(u16*)&g_vt_l[base + N_] = l1;
                    }
                } else {
                    v0 += pbias[gc];
                    v1 += pbias[gc + 1];
                    *(float2*)&out[gr * HD_ + gc] = make_float2(v0, v1);
                }
            }
        }
    }
}

// ---------------------------------------------------------------------------
// Flash attention: 128 q-rows per block (one (b,h)), 8 warps, warp m16 x n64.
// Q fragments in registers; K double-buffered + V pipelined via cp.async.
// ---------------------------------------------------------------------------
__global__ __launch_bounds__(256, 1) void flash_kernel()
{
    __shared__ u32 sKh[2][64 * 32], sKl[2][64 * 32];
    __shared__ u32 sVh[64 * 32], sVl[64 * 32];

    int tid = threadIdx.x, lane = tid & 31, wid = tid >> 5;
    int g = lane >> 2, t = lane & 3;
    int nt = blockIdx.x, h = blockIdx.y, b = blockIdx.z;
    int bh = b * H_ + h;

    const __nv_bfloat16* Kh  = g_qkv_h[1] + bh * N_ * DH_;
    const __nv_bfloat16* Kl  = g_qkv_l[1] + bh * N_ * DH_;
    const __nv_bfloat16* Vth = g_vt_h + bh * DH_ * N_;
    const __nv_bfloat16* Vtl = g_vt_l + bh * DH_ * N_;

    // Prologue: K(0), V(0), K(1) in flight
    cpa_tile64(sKh[0], Kh, DH_, tid);
    cpa_tile64(sKl[0], Kl, DH_, tid);
    cp_commit();
    cpa_tile64(sVh, Vth, N_, tid);
    cpa_tile64(sVl, Vtl, N_, tid);
    cp_commit();
    cpa_tile64(sKh[1], Kh + 64 * DH_, DH_, tid);
    cpa_tile64(sKl[1], Kl + 64 * DH_, DH_, tid);
    cp_commit();

    // Q fragments -> registers (row-major gmem, no swizzle)
    int qrow = bh * N_ + nt * 128 + wid * 16;
    const u32* qhp = (const u32*)(g_qkv_h[0] + qrow * DH_);
    const u32* qlp = (const u32*)(g_qkv_l[0] + qrow * DH_);
    u32 qfh[4][4], qfl[4][4];
    #pragma unroll
    for (int kk = 0; kk < 4; kk++) {
        qfh[kk][0] = qhp[g * 32       + kk * 8 + t];
        qfh[kk][1] = qhp[(g + 8) * 32 + kk * 8 + t];
        qfh[kk][2] = qhp[g * 32       + kk * 8 + 4 + t];
        qfh[kk][3] = qhp[(g + 8) * 32 + kk * 8 + 4 + t];
        qfl[kk][0] = qlp[g * 32       + kk * 8 + t];
        qfl[kk][1] = qlp[(g + 8) * 32 + kk * 8 + t];
        qfl[kk][2] = qlp[g * 32       + kk * 8 + 4 + t];
        qfl[kk][3] = qlp[(g + 8) * 32 + kk * 8 + 4 + t];
    }

    float o[8][4] = {};
    float mprev[2] = {-1e30f, -1e30f};
    float l[2] = {0.f, 0.f};

    cp_wait<2>();       // K(0) done
    __syncthreads();

    for (int i = 0; i < 32; i++) {
        int cur = i & 1;

        // S = Q * K^T
        float s[8][4] = {};
        #pragma unroll
        for (int kk = 0; kk < 4; kk++) {
            #pragma unroll
            for (int j = 0; j < 8; j++) {
                u32 bhf[2], blf[2];
                load_bfrag(bhf, sKh[cur], j * 8, kk, g, t);
                load_bfrag(blf, sKl[cur], j * 8, kk, g, t);
                mma_bf16(s[j][0], s[j][1], s[j][2], s[j][3], qfh[kk], bhf);
                mma_bf16(s[j][0], s[j][1], s[j][2], s[j][3], qfh[kk], blf);
                mma_bf16(s[j][0], s[j][1], s[j][2], s[j][3], qfl[kk], bhf);
            }
        }

        cp_wait<1>();   // V(i) done (mine)

        // Online softmax (register-only; rows g and g+8 spread over t lanes)
        #pragma unroll
        for (int half = 0; half < 2; half++) {
            float mx = -1e30f;
            #pragma unroll
            for (int j = 0; j < 8; j++)
                mx = fmaxf(mx, fmaxf(s[j][2 * half], s[j][2 * half + 1]));
            mx = fmaxf(mx, __shfl_xor_sync(0xffffffffu, mx, 1));
            mx = fmaxf(mx, __shfl_xor_sync(0xffffffffu, mx, 2));
            float mnew = fmaxf(mprev[half], mx);
            float corr = __expf(mprev[half] - mnew);
            float rs = 0.f;
            #pragma unroll
            for (int j = 0; j < 8; j++) {
                s[j][2 * half]     = __expf(s[j][2 * half]     - mnew);
                s[j][2 * half + 1] = __expf(s[j][2 * half + 1] - mnew);
                rs += s[j][2 * half] + s[j][2 * half + 1];
            }
            rs += __shfl_xor_sync(0xffffffffu, rs, 1);
            rs += __shfl_xor_sync(0xffffffffu, rs, 2);
            l[half] = l[half] * corr + rs;
            mprev[half] = mnew;
            #pragma unroll
            for (int j = 0; j < 8; j++) {
                o[j][2 * half]     *= corr;
                o[j][2 * half + 1] *= corr;
            }
        }

        __syncthreads();    // everyone's V(i) visible; K(cur) reads all done

        // O += P * V^T-tile; P from S regs directly as A fragments
        #pragma unroll
        for (int ka = 0; ka < 4; ka++) {
            u32 ah[4], al[4];
            split_pack(s[2 * ka][0],     s[2 * ka][1],     ah[0], al[0]);
            split_pack(s[2 * ka][2],     s[2 * ka][3],     ah[1], al[1]);
            split_pack(s[2 * ka + 1][0], s[2 * ka + 1][1], ah[2], al[2]);
            split_pack(s[2 * ka + 1][2], s[2 * ka + 1][3], ah[3], al[3]);
            #pragma unroll
            for (int j = 0; j < 8; j++) {
                u32 bhf[2], blf[2];
                load_bfrag(bhf, sVh, j * 8, ka, g, t);
                load_bfrag(blf, sVl, j * 8, ka, g, t);
                mma_bf16(o[j][0], o[j][1], o[j][2], o[j][3], ah, bhf);
                mma_bf16(o[j][0], o[j][1], o[j][2], o[j][3], ah, blf);
                mma_bf16(o[j][0], o[j][1], o[j][2], o[j][3], al, bhf);
            }
        }

        __syncthreads();    // V buffer + K(cur) free for refill

        int vm = (i + 1 < 32) ? i + 1 : 31;
        int km = (i + 2 < 32) ? i + 2 : 31;
        cpa_tile64(sVh, Vth + vm * 64, N_, tid);
        cpa_tile64(sVl, Vtl + vm * 64, N_, tid);
        cp_commit();
        cpa_tile64(sKh[cur], Kh + km * 64 * DH_, DH_, tid);
        cpa_tile64(sKl[cur], Kl + km * 64 * DH_, DH_, tid);
        cp_commit();
        cp_wait<2>();       // K(i+1) done
        __syncthreads();
    }
    cp_wait<0>();

    // Normalize and split-store to g_mh [B*N][H*DH]
    #pragma unroll
    for (int half = 0; half < 2; half++) {
        float inv = 1.0f / l[half];
        int n = nt * 128 + wid * 16 + g + 8 * half;
        int row = b * N_ + n;
        #pragma unroll
        for (int j = 0; j < 8; j++) {
            int col = h * DH_ + j * 8 + 2 * t;
            u32 hw, lw;
            split_pack(o[j][2 * half] * inv, o[j][2 * half + 1] * inv, hw, lw);
            *(u32*)&g_mh_h[row * HD_ + col] = hw;
            *(u32*)&g_mh_l[row * HD_ + col] = lw;
        }
    }
}

// ---------------------------------------------------------------------------
// Launch
// ---------------------------------------------------------------------------
extern "C" void kernel_launch(void* const* d_in, const int* in_sizes, int n_in,
                              void* d_out, int out_size)
{
    const float* query = (const float*)d_in[0];
    const float* key   = (const float*)d_in[1];
    const float* value = (const float*)d_in[2];
    const float* wq    = (const float*)d_in[3];
    const float* wk    = (const float*)d_in[4];
    const float* wv    = (const float*)d_in[5];
    const float* wp    = (const float*)d_in[6];
    const float* bq    = (const float*)d_in[7];
    const float* bk    = (const float*)d_in[8];
    const float* bv    = (const float*)d_in[9];
    const float* pb    = (const float*)d_in[10];
    float* out = (float*)d_out;
    (void)in_sizes; (void)n_in; (void)out_size;

    int acts_threads = 3 * (ROWS_ * DM_ / 4);
    conv_acts<<<(acts_threads + 255) / 256, 256>>>(query, key, value);

    int w_threads = 3 * (HD_ * DM_ / 4) + (HD_ * HD_ / 4) + 3 * HD_;
    conv_w<<<(w_threads + 255) / 256, 256>>>(wq, wk, wv, wp, bq, bk, bv);

    dim3 gq(HD_ / 64, ROWS_ / 128, 3);
    gemm_kernel<0><<<gq, 256>>>(nullptr, nullptr);

    dim3 gf(N_ / 128, H_, B_);
    flash_kernel<<<gf, 256>>>();

    dim3 gp(HD_ / 64, ROWS_ / 128);
    gemm_kernel<1><<<gp, 256>>>(pb, out);
}